// round 10
// baseline (speedup 1.0000x reference)
#include <cuda_runtime.h>
#include <cuda_bf16.h>
#include <cstdint>
#include <cmath>

// Problem:
//   x: [B=64, C=256, N=4096] f32;  weight: [F=512, C=256, 3, 3] f32
//   epsilon: [S, F, C, 3, 3] f32;  out: [S, B, F, 4096] f32
// Identity: kernel dims never index x ->
//   Weff[s,f,c] = sum_{k,l} tanh(w + 0.5*log(eps/(1-eps)))
//   out[s,b,f,n] = sum_c Weff[s,f,c] * x[b,c,n]   (batched 512x4096x256 GEMM)
// HMMA split-bf16 (hi/lo, 3 passes: hh+hl+lh, fp32 accum) -> rel_err ~5e-6.
// This round: x pre-split to bf16 hi/lo AND pre-transposed to [b][n][c] so the
// GEMM is a pure cp.async-fed tensor pipeline (no in-loop conversion/transpose).

#define F_DIM 512
#define C_DIM 256
#define B_DIM 64
#define N_DIM 4096
#define KK_DIM 9
#define MAX_S 4

#define TM 128
#define TN 64
#define TK 64
#define NCHUNK (C_DIM / TK)          // 4

// SMEM stage: A hi/lo (128 rows x 128B) + B hi/lo (64 rows x 128B), SW128-XOR
#define OFF_AH 0
#define OFF_AL 16384
#define OFF_BH 32768
#define OFF_BL 40960
#define STAGE_B 49152
#define SMEM_SZ (2 * STAGE_B)        // 98304 -> 2 CTAs/SM

__device__ __nv_bfloat16 g_wh[MAX_S * F_DIM * C_DIM];
__device__ __nv_bfloat16 g_wl[MAX_S * F_DIM * C_DIM];
// x split + transposed: [b][n][c] bf16 (134 MB each)
__device__ __nv_bfloat16 g_xh[(size_t)B_DIM * N_DIM * C_DIM];
__device__ __nv_bfloat16 g_xl[(size_t)B_DIM * N_DIM * C_DIM];

// ---------------------------------------------------------------------------
// Kernel 1: effective weights -> bf16 hi/lo
// ---------------------------------------------------------------------------
__global__ void weff_kernel(const float* __restrict__ w,
                            const float* __restrict__ eps, int S) {
    int i = blockIdx.x * blockDim.x + threadIdx.x;
    int total = S * F_DIM * C_DIM;
    if (i >= total) return;
    int fc = i % (F_DIM * C_DIM);
    const float* wp = w + (size_t)fc * KK_DIM;
    const float* ep = eps + (size_t)i * KK_DIM;
    float acc = 0.0f;
#pragma unroll
    for (int j = 0; j < KK_DIM; j++) {
        float e = ep[j];
        acc += tanhf(wp[j] + 0.5f * logf(e / (1.0f - e)));
    }
    __nv_bfloat16 h = __float2bfloat16_rn(acc);
    g_wh[i] = h;
    g_wl[i] = __float2bfloat16_rn(acc - __bfloat162float(h));
}

// ---------------------------------------------------------------------------
// Kernel 2: x [b][c][n] f32 -> g_xh/g_xl [b][n][c] bf16 (tiled transpose)
// block(32,8), tile 32x32, grid(N/32, C/32, B)
// ---------------------------------------------------------------------------
__global__ void __launch_bounds__(256)
xsplit_kernel(const float* __restrict__ x) {
    __shared__ float tile[32][33];
    const int n0 = blockIdx.x * 32, c0 = blockIdx.y * 32, b = blockIdx.z;
    const int tx = threadIdx.x, ty = threadIdx.y;
    const float* src = x + ((size_t)b * C_DIM + c0) * N_DIM + n0;
#pragma unroll
    for (int i = 0; i < 4; i++)
        tile[ty + i * 8][tx] = src[(size_t)(ty + i * 8) * N_DIM + tx];
    __syncthreads();
    const int idx = ty * 32 + tx;
    const int cl = (idx & 15) * 2;           // local c pair
    const int nl = idx >> 4;                 // local n (0..15), rows nl, nl+16
    const size_t obase = ((size_t)b * N_DIM + n0) * C_DIM + c0 + cl;
#pragma unroll
    for (int r = 0; r < 2; r++) {
        int nr = nl + r * 16;
        float f0 = tile[cl][nr], f1 = tile[cl + 1][nr];
        __nv_bfloat16 h0 = __float2bfloat16_rn(f0);
        __nv_bfloat16 h1 = __float2bfloat16_rn(f1);
        __nv_bfloat16 l0 = __float2bfloat16_rn(f0 - __bfloat162float(h0));
        __nv_bfloat16 l1 = __float2bfloat16_rn(f1 - __bfloat162float(h1));
        uint32_t hp = (uint32_t)__bfloat16_as_ushort(h0) |
                      ((uint32_t)__bfloat16_as_ushort(h1) << 16);
        uint32_t lp = (uint32_t)__bfloat16_as_ushort(l0) |
                      ((uint32_t)__bfloat16_as_ushort(l1) << 16);
        *(uint32_t*)(g_xh + obase + (size_t)nr * C_DIM) = hp;
        *(uint32_t*)(g_xl + obase + (size_t)nr * C_DIM) = lp;
    }
}

// ---------------------------------------------------------------------------
// Helpers
// ---------------------------------------------------------------------------
__device__ __forceinline__ uint32_t smem_u32(const void* p) {
    uint32_t a;
    asm("{ .reg .u64 t; cvta.to.shared.u64 t, %1; cvt.u32.u64 %0, t; }"
        : "=r"(a) : "l"(p));
    return a;
}
__device__ __forceinline__ void cpasync16(uint32_t dst, const void* src) {
    asm volatile("cp.async.cg.shared.global [%0], [%1], 16;"
                 :: "r"(dst),
                    "l"((unsigned long long)__cvta_generic_to_global(src))
                 : "memory");
}
#define CP_COMMIT() asm volatile("cp.async.commit_group;" ::: "memory")
#define CP_WAIT1()  asm volatile("cp.async.wait_group 1;" ::: "memory")
#define CP_WAIT0()  asm volatile("cp.async.wait_group 0;" ::: "memory")

#define LDM4(r, addr)                                                       \
    asm volatile("ldmatrix.sync.aligned.m8n8.x4.shared.b16 "                \
                 "{%0,%1,%2,%3}, [%4];"                                     \
                 : "=r"((r)[0]), "=r"((r)[1]), "=r"((r)[2]), "=r"((r)[3])   \
                 : "r"(addr))
#define MMA(c, a, b0, b1)                                                   \
    asm volatile("mma.sync.aligned.m16n8k16.row.col.f32.bf16.bf16.f32 "     \
                 "{%0,%1,%2,%3}, {%4,%5,%6,%7}, {%8,%9}, {%0,%1,%2,%3};"    \
                 : "+f"((c)[0]), "+f"((c)[1]), "+f"((c)[2]), "+f"((c)[3])   \
                 : "r"((a)[0]), "r"((a)[1]), "r"((a)[2]), "r"((a)[3]),      \
                   "r"(b0), "r"(b1))

// ---------------------------------------------------------------------------
// Kernel 3: GEMM. CTA 128(M=f) x 64(N=n), 4 warps (2m x 2n), warp 64x32.
// cp.async double-buffered, SW128-XOR swizzled 128B rows, ldmatrix non-trans
// (R9-proven fragment mappings), 3 bf16 passes, fp32 accum.
// ---------------------------------------------------------------------------
__global__ void __launch_bounds__(128)
gemm_mma(float* __restrict__ out) {
    extern __shared__ char smem[];
    const uint32_t sb = smem_u32(smem);
    const int tid = threadIdx.x;
    const int wid = tid >> 5, lane = tid & 31;

    const int n0 = blockIdx.x * TN;
    const int m0 = blockIdx.y * TM;
    const int bz = blockIdx.z;                  // s*64 + b
    const int s = bz >> 6, b = bz & 63;

    const __nv_bfloat16* Agh = g_wh + (size_t)s * F_DIM * C_DIM;
    const __nv_bfloat16* Agl = g_wl + (size_t)s * F_DIM * C_DIM;
    const __nv_bfloat16* Xh = g_xh + (size_t)b * N_DIM * C_DIM;
    const __nv_bfloat16* Xl = g_xl + (size_t)b * N_DIM * C_DIM;

    // loader lane geometry
    const int brow = tid & 63, bhalf = tid >> 6;        // B: 4 chunks/thread/mat
    // warp tile bases
    const int mbw = (wid & 1) * 64, nbw = (wid >> 1) * 32;
    // ldmatrix lane geometry (R9-proven mappings)
    const int a_row = lane & 15;                        // A: rows m0-15
    const int a_ci0 = lane >> 4;                        // A: k-chunk 0/1
    const int b_row = (lane & 7) + (lane >> 4) * 8;     // B: rows n0-15
    const int b_ci0 = (lane >> 3) & 1;                  // B: k-chunk 0/1
    const int sw = lane & 7;                            // XOR swizzle key

    float acc[4][4][4];
#pragma unroll
    for (int mt = 0; mt < 4; mt++)
#pragma unroll
        for (int j = 0; j < 4; j++)
#pragma unroll
            for (int q = 0; q < 4; q++) acc[mt][j][q] = 0.0f;

    // ---- stage loader (cp.async): 24 x 16B per thread ----
    auto load_stage = [&](int t, int buf) {
        const uint32_t base = sb + (uint32_t)buf * STAGE_B;
        const int c0 = t * TK;
        const __nv_bfloat16* ah = Agh + (size_t)(m0 + tid) * C_DIM + c0;
        const __nv_bfloat16* al = Agl + (size_t)(m0 + tid) * C_DIM + c0;
        const uint32_t arow_off = (uint32_t)tid * 128;
        const int akey = tid & 7;
#pragma unroll
        for (int q = 0; q < 8; q++) {
            uint32_t d = arow_off + (uint32_t)((q ^ akey) << 4);
            cpasync16(base + OFF_AH + d, ah + q * 8);
            cpasync16(base + OFF_AL + d, al + q * 8);
        }
        const __nv_bfloat16* bh =
            Xh + (size_t)(n0 + brow) * C_DIM + c0;
        const __nv_bfloat16* bl =
            Xl + (size_t)(n0 + brow) * C_DIM + c0;
        const uint32_t brow_off = (uint32_t)brow * 128;
        const int bkey = brow & 7;
#pragma unroll
        for (int j = 0; j < 4; j++) {
            int q = bhalf * 4 + j;
            uint32_t d = brow_off + (uint32_t)((q ^ bkey) << 4);
            cpasync16(base + OFF_BH + d, bh + q * 8);
            cpasync16(base + OFF_BL + d, bl + q * 8);
        }
    };

    load_stage(0, 0); CP_COMMIT();
    load_stage(1, 1); CP_COMMIT();

#pragma unroll 1
    for (int t = 0; t < NCHUNK; t++) {
        if (t < NCHUNK - 1) { CP_WAIT1(); } else { CP_WAIT0(); }
        __syncthreads();

        const uint32_t base = sb + (uint32_t)(t & 1) * STAGE_B;
#pragma unroll
        for (int k = 0; k < 4; k++) {
            uint32_t Ah[4][4], Al[4][4], Bh[2][4], Bl[2][4];
#pragma unroll
            for (int mt = 0; mt < 4; mt++) {
                uint32_t ra = base +
                    (uint32_t)((mbw + mt * 16 + a_row) * 128) +
                    (uint32_t)((((k * 2 + a_ci0) ^ sw)) << 4);
                LDM4(Ah[mt], ra + OFF_AH);
                LDM4(Al[mt], ra + OFF_AL);
            }
#pragma unroll
            for (int nt = 0; nt < 2; nt++) {
                uint32_t rb = base +
                    (uint32_t)((nbw + nt * 16 + b_row) * 128) +
                    (uint32_t)((((k * 2 + b_ci0) ^ sw)) << 4);
                LDM4(Bh[nt], rb + OFF_BH);
                LDM4(Bl[nt], rb + OFF_BL);
            }
#pragma unroll
            for (int mt = 0; mt < 4; mt++)
#pragma unroll
                for (int j = 0; j < 4; j++) {
                    const int nt = j >> 1, i = (j & 1) * 2;
                    MMA(acc[mt][j], Ah[mt], Bh[nt][i], Bh[nt][i + 1]);
                    MMA(acc[mt][j], Ah[mt], Bl[nt][i], Bl[nt][i + 1]);
                    MMA(acc[mt][j], Al[mt], Bh[nt][i], Bh[nt][i + 1]);
                }
        }
        __syncthreads();
        if (t + 2 < NCHUNK) { load_stage(t + 2, t & 1); CP_COMMIT(); }
    }

    // ---- epilogue ----
#pragma unroll
    for (int mt = 0; mt < 4; mt++)
#pragma unroll
        for (int j = 0; j < 4; j++) {
            const int row = m0 + mbw + mt * 16 + (lane >> 2);
            const int col = n0 + nbw + j * 8 + (lane & 3) * 2;
            float* op = out + ((size_t)bz * F_DIM + row) * N_DIM + col;
            *(float2*)op = make_float2(acc[mt][j][0], acc[mt][j][1]);
            *(float2*)(op + 8 * N_DIM) =
                make_float2(acc[mt][j][2], acc[mt][j][3]);
        }
}

// ---------------------------------------------------------------------------
// Launch: inputs in metadata order: x, weight, epsilon
// ---------------------------------------------------------------------------
extern "C" void kernel_launch(void* const* d_in, const int* in_sizes, int n_in,
                              void* d_out, int out_size) {
    const float* x   = (const float*)d_in[0];
    const float* w   = (const float*)d_in[1];
    const float* eps = (const float*)d_in[2];
    float* out = (float*)d_out;

    int S = in_sizes[2] / in_sizes[1];
    if (S < 1) S = 1;
    if (S > MAX_S) S = MAX_S;

    int total = S * F_DIM * C_DIM;
    weff_kernel<<<(total + 255) / 256, 256>>>(w, eps, S);

    dim3 tgrid(N_DIM / 32, C_DIM / 32, B_DIM);
    xsplit_kernel<<<tgrid, dim3(32, 8)>>>(x);

    cudaFuncSetAttribute(gemm_mma, cudaFuncAttributeMaxDynamicSharedMemorySize,
                         SMEM_SZ);
    dim3 grid(N_DIM / TN, F_DIM / TM, S * B_DIM);
    gemm_mma<<<grid, 128, SMEM_SZ>>>(out);
}